// round 1
// baseline (speedup 1.0000x reference)
#include <cuda_runtime.h>
#include <math.h>

#define B_ 4
#define L_ 384
#define H_ 128
#define F_ 384

// SMEM leading dims (floats), padded to avoid bank conflicts
#define LDA1 388
#define LDE  132
#define LDW  132

__device__ float g_acc[B_];

__device__ __forceinline__ float gelu_f(float x) {
    return 0.5f * x * (1.0f + erff(x * 0.7071067811865475f));
}

// C[64 x 128] += A[64 x (NKS*64)] @ W[:, c0:c0+128], W row-major with stride F_.
// A is in SMEM with leading dim LDA; W slices are staged through sW.
template <int LDA, int NKS>
__device__ __forceinline__ void gemm_chunk(
    const float* __restrict__ sA, const float* __restrict__ W, int c0,
    float* __restrict__ sW, int tid, int r0, int c0t, float acc[4][8])
{
#pragma unroll
    for (int i = 0; i < 4; ++i)
#pragma unroll
        for (int j = 0; j < 8; ++j) acc[i][j] = 0.f;

    for (int ks = 0; ks < NKS; ++ks) {
        // stage 64x128 slice of W into sW
#pragma unroll
        for (int i = 0; i < 8; ++i) {
            int id  = tid + i * 256;
            int row = id >> 5;
            int c4  = (id & 31) * 4;
            float4 v = *(const float4*)(W + (size_t)(ks * 64 + row) * F_ + c0 + c4);
            *(float4*)(sW + row * LDW + c4) = v;
        }
        __syncthreads();

        const float* Abase = sA + ks * 64;
#pragma unroll 8
        for (int k = 0; k < 64; ++k) {
            float a0 = Abase[(r0 + 0) * LDA + k];
            float a1 = Abase[(r0 + 1) * LDA + k];
            float a2 = Abase[(r0 + 2) * LDA + k];
            float a3 = Abase[(r0 + 3) * LDA + k];
            float4 b0 = *(const float4*)(sW + k * LDW + c0t);
            float4 b1 = *(const float4*)(sW + k * LDW + c0t + 4);
            float bb[8] = {b0.x, b0.y, b0.z, b0.w, b1.x, b1.y, b1.z, b1.w};
#pragma unroll
            for (int j = 0; j < 8; ++j) {
                acc[0][j] += a0 * bb[j];
                acc[1][j] += a1 * bb[j];
                acc[2][j] += a2 * bb[j];
                acc[3][j] += a3 * bb[j];
            }
        }
        __syncthreads();
    }
}

__global__ __launch_bounds__(256, 1) void fused_main(
    const float* __restrict__ hV,  const float* __restrict__ hE,
    const float* __restrict__ mask,
    const float* __restrict__ fw1, const float* __restrict__ fb1,
    const float* __restrict__ fw2, const float* __restrict__ fb2,
    const float* __restrict__ hw1, const float* __restrict__ hb1,
    const float* __restrict__ hw2, const float* __restrict__ hb2,
    const float* __restrict__ hw3, const float* __restrict__ hb3)
{
    extern __shared__ float sm[];
    float* sA1   = sm;                   // 64*388
    float* sE    = sA1 + 64 * LDA1;      // 64*132 (E tile; reused as Wf tile)
    float* sW    = sE  + 64 * LDE;       // 64*132 (weight staging)
    float* xcv   = sW  + 64 * LDW;       // 384
    float* sPart = xcv + 384;            // 256
    float* sH1   = sPart + 256;          // 128
    float* sH2   = sH1 + 128;            // 64

    const int tid = threadIdx.x;
    const int l   = blockIdx.x;
    const int b   = blockIdx.y;
    const int tr  = tid >> 4;
    const int tc  = tid & 15;
    const int r0  = tr * 4;
    const int c0t = tc * 8;

    float xacc0 = 0.f, xacc1 = 0.f, xacc2 = 0.f;

    const float* hE_base = hE + ((size_t)(b * L_ + l)) * L_ * H_;

    for (int kt = 0; kt < 6; ++kt) {
        const int k0 = kt * 64;

        // load E tile [64 x 128] (rows k, cols h)
        {
            const float* src = hE_base + (size_t)k0 * H_;
#pragma unroll
            for (int i = 0; i < 8; ++i) {
                int id  = tid + i * 256;
                int row = id >> 5;
                int c4  = (id & 31) * 4;
                float4 v = *(const float4*)(src + (size_t)row * H_ + c4);
                *(float4*)(sE + row * LDE + c4) = v;
            }
        }
        __syncthreads();

        // GEMM1: A1 = gelu(E @ fw1 + fb1), written to sA1
        for (int fc = 0; fc < 3; ++fc) {
            float acc[4][8];
            gemm_chunk<LDE, 2>(sE, fw1, fc * 128, sW, tid, r0, c0t, acc);
#pragma unroll
            for (int i = 0; i < 4; ++i)
#pragma unroll
                for (int j = 0; j < 8; ++j) {
                    float v = acc[i][j] + fb1[fc * 128 + c0t + j];
                    sA1[(r0 + i) * LDA1 + fc * 128 + c0t + j] = gelu_f(v);
                }
        }
        __syncthreads();

        // GEMM2: Wf = gelu(A1 @ fw2 + fb2), then contract with h_V over k
        for (int fc = 0; fc < 3; ++fc) {
            float acc[4][8];
            gemm_chunk<LDA1, 6>(sA1, fw2, fc * 128, sW, tid, r0, c0t, acc);
            // gelu -> Wf tile into sE buffer (E no longer needed this k-tile)
#pragma unroll
            for (int i = 0; i < 4; ++i)
#pragma unroll
                for (int j = 0; j < 8; ++j) {
                    float v = acc[i][j] + fb2[fc * 128 + c0t + j];
                    sE[(r0 + i) * LDE + c0t + j] = gelu_f(v);
                }
            __syncthreads();

            // x_conv[f] += sum_k hV[b, k0+k, f] * Wf[k, f]
            {
                int fl   = tid & 127;
                int half = tid >> 7;
                const float* hv = hV + ((size_t)(b * L_) + k0 + half * 32) * F_ + fc * 128 + fl;
                float p = 0.f;
#pragma unroll 8
                for (int k = 0; k < 32; ++k)
                    p += hv[(size_t)k * F_] * sE[(half * 32 + k) * LDE + fl];
                sPart[half * 128 + fl] = p;
            }
            __syncthreads();
            if (tid < 128) {
                float v = sPart[tid] + sPart[128 + tid];
                if (fc == 0)      xacc0 += v;
                else if (fc == 1) xacc1 += v;
                else              xacc2 += v;
            }
            __syncthreads();
        }
    }

    // gather x_conv
    if (tid < 128) {
        xcv[tid]       = xacc0;
        xcv[128 + tid] = xacc1;
        xcv[256 + tid] = xacc2;
    }
    __syncthreads();

    // head MLP: F->H gelu, H->H/2 gelu, H/2->1
    if (tid < 128) {
        float s = hb1[tid];
#pragma unroll 4
        for (int i = 0; i < F_; ++i) s += xcv[i] * hw1[i * H_ + tid];
        sH1[tid] = gelu_f(s);
    }
    __syncthreads();
    if (tid < 64) {
        float s = hb2[tid];
#pragma unroll 4
        for (int i = 0; i < H_; ++i) s += sH1[i] * hw2[i * 64 + tid];
        sH2[tid] = gelu_f(s);
    }
    __syncthreads();
    if (tid < 32) {
        float p = sH2[tid] * hw3[tid] + sH2[tid + 32] * hw3[tid + 32];
#pragma unroll
        for (int o = 16; o > 0; o >>= 1) p += __shfl_down_sync(0xffffffffu, p, o);
        if (tid == 0) {
            float pred = p + hb3[0];
            atomicAdd(&g_acc[b], pred * mask[b * L_ + l]);
        }
    }
}

__global__ void zero_acc_k() {
    if (threadIdx.x < B_) g_acc[threadIdx.x] = 0.f;
}

__global__ void finalize_k(const float* __restrict__ mask, float* __restrict__ out) {
    int b    = threadIdx.y;   // blockDim = (32, 4)
    int lane = threadIdx.x;
    float s = 0.f;
    for (int l = lane; l < L_; l += 32) s += mask[b * L_ + l];
#pragma unroll
    for (int o = 16; o > 0; o >>= 1) s += __shfl_down_sync(0xffffffffu, s, o);
    if (lane == 0) {
        float vl = fmaxf(s, 1.0f);
        out[b] = g_acc[b] / sqrtf(vl);
    }
}

extern "C" void kernel_launch(void* const* d_in, const int* in_sizes, int n_in,
                              void* d_out, int out_size)
{
    const float* hV   = (const float*)d_in[0];
    const float* hE   = (const float*)d_in[1];
    const float* mask = (const float*)d_in[2];
    const float* fw1  = (const float*)d_in[3];
    const float* fb1  = (const float*)d_in[4];
    const float* fw2  = (const float*)d_in[5];
    const float* fb2  = (const float*)d_in[6];
    const float* hw1  = (const float*)d_in[7];
    const float* hb1  = (const float*)d_in[8];
    const float* hw2  = (const float*)d_in[9];
    const float* hb2  = (const float*)d_in[10];
    const float* hw3  = (const float*)d_in[11];
    const float* hb3  = (const float*)d_in[12];
    float* out = (float*)d_out;

    const int smem_bytes = (64 * LDA1 + 64 * LDE + 64 * LDW + 384 + 256 + 128 + 64) * 4;
    cudaFuncSetAttribute(fused_main, cudaFuncAttributeMaxDynamicSharedMemorySize, smem_bytes);

    zero_acc_k<<<1, 32>>>();
    dim3 grid(L_, B_);
    fused_main<<<grid, 256, smem_bytes>>>(hV, hE, mask, fw1, fb1, fw2, fb2,
                                          hw1, hb1, hw2, hb2, hw3, hb3);
    finalize_k<<<1, dim3(32, B_)>>>(mask, out);
}

// round 4
// speedup vs baseline: 2.7528x; 2.7528x over previous
#include <cuda_runtime.h>
#include <cuda_bf16.h>
#include <math.h>
#include <stdint.h>

#define B_ 4
#define L_ 384
#define H_ 128
#define F_ 384

typedef unsigned short ushort_t;

// ---------------- device scratch: transposed hi/lo bf16 weight images --------
// layout [n][k], k contiguous
__device__ __align__(16) ushort_t g_fw1T_h[F_ * H_];   // 384 x 128
__device__ __align__(16) ushort_t g_fw1T_l[F_ * H_];
__device__ __align__(16) ushort_t g_fw2T_h[F_ * F_];   // 384 x 384
__device__ __align__(16) ushort_t g_fw2T_l[F_ * F_];
__device__ float g_acc[B_];

// ---------------- smem layout (bytes) ----------------------------------------
#define LDE   136   // halves per row (E tiles: 64 x 128)
#define LDW   136   // halves per row (W tiles: 128 x 128)
#define LDA1  392   // halves per row (A1: 64 x 384)
#define LDWF  132   // floats per row (Wf: 64 x 128)

#define SM_E_H   0
#define SM_E_L   17408
#define SM_A1H   34816
#define SM_A1L   84992
#define SM_WH    135168
#define SM_WL    169984
#define SM_XCV   204800
#define SM_PART  206336
#define SM_H1    207360
#define SM_H2    207872
#define SM_TOTAL 208128
// Wf (fp32 64x132 = 33792B) aliases the E region at offset 0.

__device__ __forceinline__ float gelu_f(float x) {
    return 0.5f * x * (1.0f + erff(x * 0.7071067811865475f));
}

__device__ __forceinline__ void split_bf(float x, ushort_t& hi, ushort_t& lo) {
    __nv_bfloat16 h = __float2bfloat16(x);
    __nv_bfloat16 l = __float2bfloat16(x - __bfloat162float(h));
    hi = __bfloat16_as_ushort(h);
    lo = __bfloat16_as_ushort(l);
}

__device__ __forceinline__ void mma16816(float d[4], uint32_t a0, uint32_t a1,
                                         uint32_t a2, uint32_t a3,
                                         uint32_t b0, uint32_t b1) {
    asm volatile(
        "mma.sync.aligned.m16n8k16.row.col.f32.bf16.bf16.f32 "
        "{%0,%1,%2,%3}, {%4,%5,%6,%7}, {%8,%9}, {%0,%1,%2,%3};"
        : "+f"(d[0]), "+f"(d[1]), "+f"(d[2]), "+f"(d[3])
        : "r"(a0), "r"(a1), "r"(a2), "r"(a3), "r"(b0), "r"(b1));
}

// 8 k-steps (k=128) of the 3-pass hi/lo MMA over a 32x32 warp tile
template <int LDA>
__device__ __forceinline__ void do_ksteps(
    const ushort_t* __restrict__ sAh, const ushort_t* __restrict__ sAl,
    const ushort_t* __restrict__ sWh, const ushort_t* __restrict__ sWl,
    int m0w, int n0w, int g, int t, float acc[2][4][4])
{
#pragma unroll
    for (int ks = 0; ks < 8; ++ks) {
        const int ka = ks * 16 + t * 2;
        uint32_t Ah[2][4], Al[2][4], Bh[4][2], Bl[4][2];
#pragma unroll
        for (int mi = 0; mi < 2; ++mi) {
            const ushort_t* p = sAh + (m0w + mi * 16 + g) * LDA + ka;
            Ah[mi][0] = *(const uint32_t*)p;
            Ah[mi][1] = *(const uint32_t*)(p + 8 * LDA);
            Ah[mi][2] = *(const uint32_t*)(p + 8);
            Ah[mi][3] = *(const uint32_t*)(p + 8 * LDA + 8);
            const ushort_t* q = sAl + (m0w + mi * 16 + g) * LDA + ka;
            Al[mi][0] = *(const uint32_t*)q;
            Al[mi][1] = *(const uint32_t*)(q + 8 * LDA);
            Al[mi][2] = *(const uint32_t*)(q + 8);
            Al[mi][3] = *(const uint32_t*)(q + 8 * LDA + 8);
        }
#pragma unroll
        for (int ni = 0; ni < 4; ++ni) {
            const ushort_t* p = sWh + (n0w + ni * 8 + g) * LDW + ka;
            Bh[ni][0] = *(const uint32_t*)p;
            Bh[ni][1] = *(const uint32_t*)(p + 8);
            const ushort_t* q = sWl + (n0w + ni * 8 + g) * LDW + ka;
            Bl[ni][0] = *(const uint32_t*)q;
            Bl[ni][1] = *(const uint32_t*)(q + 8);
        }
#pragma unroll
        for (int mi = 0; mi < 2; ++mi)
#pragma unroll
            for (int ni = 0; ni < 4; ++ni) {
                mma16816(acc[mi][ni], Ah[mi][0], Ah[mi][1], Ah[mi][2], Ah[mi][3],
                         Bh[ni][0], Bh[ni][1]);
                mma16816(acc[mi][ni], Ah[mi][0], Ah[mi][1], Ah[mi][2], Ah[mi][3],
                         Bl[ni][0], Bl[ni][1]);
                mma16816(acc[mi][ni], Al[mi][0], Al[mi][1], Al[mi][2], Al[mi][3],
                         Bh[ni][0], Bh[ni][1]);
            }
    }
}

// ---------------- weight prep: transpose + hi/lo split ------------------------
__global__ void prep_weights(const float* __restrict__ fw1,
                             const float* __restrict__ fw2) {
    int idx = blockIdx.x * blockDim.x + threadIdx.x;
    int stride = gridDim.x * blockDim.x;
    for (int e = idx; e < F_ * H_; e += stride) {
        int n = e / H_, k = e % H_;
        ushort_t h, l;
        split_bf(fw1[(size_t)k * F_ + n], h, l);
        g_fw1T_h[e] = h; g_fw1T_l[e] = l;
    }
    for (int e = idx; e < F_ * F_; e += stride) {
        int n = e / F_, k = e % F_;
        ushort_t h, l;
        split_bf(fw2[(size_t)k * F_ + n], h, l);
        g_fw2T_h[e] = h; g_fw2T_l[e] = l;
    }
}

__global__ void zero_acc_k() {
    if (threadIdx.x < B_) g_acc[threadIdx.x] = 0.f;
}

__global__ __launch_bounds__(256, 1) void fused_mma(
    const float* __restrict__ hV,  const float* __restrict__ hE,
    const float* __restrict__ mask,
    const float* __restrict__ fb1, const float* __restrict__ fb2,
    const float* __restrict__ hw1, const float* __restrict__ hb1,
    const float* __restrict__ hw2, const float* __restrict__ hb2,
    const float* __restrict__ hw3, const float* __restrict__ hb3)
{
    extern __shared__ char smem[];
    ushort_t* sEh  = (ushort_t*)(smem + SM_E_H);
    ushort_t* sEl  = (ushort_t*)(smem + SM_E_L);
    ushort_t* sA1h = (ushort_t*)(smem + SM_A1H);
    ushort_t* sA1l = (ushort_t*)(smem + SM_A1L);
    ushort_t* sWh  = (ushort_t*)(smem + SM_WH);
    ushort_t* sWl  = (ushort_t*)(smem + SM_WL);
    float* sWf   = (float*)(smem + SM_E_H);   // alias over E (dead in GEMM2)
    float* xcv   = (float*)(smem + SM_XCV);
    float* sPart = (float*)(smem + SM_PART);
    float* sH1   = (float*)(smem + SM_H1);
    float* sH2   = (float*)(smem + SM_H2);

    const int tid  = threadIdx.x;
    const int wid  = tid >> 5;
    const int lane = tid & 31;
    const int g    = lane >> 2;   // groupID
    const int t    = lane & 3;    // thread-in-group
    const int m0w  = (wid >> 2) * 32;
    const int n0w  = (wid & 3) * 32;
    const int l = blockIdx.x, b = blockIdx.y;

    float xacc0 = 0.f, xacc1 = 0.f, xacc2 = 0.f;
    const float* hE_base = hE + (size_t)(b * L_ + l) * L_ * H_;

    for (int mt = 0; mt < 6; ++mt) {
        // ---- stage E tile [64 x 128] fp32 -> bf16 hi/lo in SMEM ----
        __syncthreads();
        {
            const float* src = hE_base + (size_t)(mt * 64) * H_;
#pragma unroll
            for (int it = 0; it < 8; ++it) {
                int gx = tid + it * 256;          // 0..2047 float4s
                int m = gx >> 5, k4 = (gx & 31) * 4;
                float4 v = *(const float4*)(src + (size_t)m * H_ + k4);
                ushort_t h0, l0, h1, l1, h2, l2, h3, l3;
                split_bf(v.x, h0, l0); split_bf(v.y, h1, l1);
                split_bf(v.z, h2, l2); split_bf(v.w, h3, l3);
                uint32_t ph0 = ((uint32_t)h1 << 16) | h0;
                uint32_t ph1 = ((uint32_t)h3 << 16) | h2;
                uint32_t pl0 = ((uint32_t)l1 << 16) | l0;
                uint32_t pl1 = ((uint32_t)l3 << 16) | l2;
                *(uint2*)&sEh[m * LDE + k4] = make_uint2(ph0, ph1);
                *(uint2*)&sEl[m * LDE + k4] = make_uint2(pl0, pl1);
            }
        }
        __syncthreads();

        // ---- GEMM1: A1 = gelu(E @ fw1 + fb1) -> sA1 hi/lo ----
        for (int nc = 0; nc < 3; ++nc) {
            __syncthreads();   // prior W-tile readers done
            {
                // fw1 image: 128 halves/row = 16 uint4 per row
                const uint4* s1h = (const uint4*)g_fw1T_h;
                const uint4* s1l = (const uint4*)g_fw1T_l;
                for (int i = tid; i < 2048; i += 256) {
                    int row = i >> 4, c = i & 15;   // row<128, 16B units (128 halves/row)
                    *(uint4*)((char*)sWh + row * (LDW * 2) + c * 16) = s1h[(size_t)(nc * 128 + row) * 16 + c];
                    *(uint4*)((char*)sWl + row * (LDW * 2) + c * 16) = s1l[(size_t)(nc * 128 + row) * 16 + c];
                }
            }
            __syncthreads();

            float acc[2][4][4];
#pragma unroll
            for (int mi = 0; mi < 2; ++mi)
#pragma unroll
                for (int ni = 0; ni < 4; ++ni)
#pragma unroll
                    for (int r = 0; r < 4; ++r) acc[mi][ni][r] = 0.f;

            do_ksteps<LDE>(sEh, sEl, sWh, sWl, m0w, n0w, g, t, acc);

            // epilogue: +bias, gelu, split, store
#pragma unroll
            for (int mi = 0; mi < 2; ++mi)
#pragma unroll
                for (int ni = 0; ni < 4; ++ni) {
                    int r = m0w + mi * 16 + g;
                    int c = nc * 128 + n0w + ni * 8 + t * 2;
                    float b0 = __ldg(&fb1[c]), b1 = __ldg(&fb1[c + 1]);
                    float g0 = gelu_f(acc[mi][ni][0] + b0);
                    float g1 = gelu_f(acc[mi][ni][1] + b1);
                    float g2 = gelu_f(acc[mi][ni][2] + b0);
                    float g3 = gelu_f(acc[mi][ni][3] + b1);
                    ushort_t h0, lo0, h1, lo1, h2, lo2, h3, lo3;
                    split_bf(g0, h0, lo0); split_bf(g1, h1, lo1);
                    split_bf(g2, h2, lo2); split_bf(g3, h3, lo3);
                    *(uint32_t*)&sA1h[r * LDA1 + c]       = ((uint32_t)h1 << 16) | h0;
                    *(uint32_t*)&sA1l[r * LDA1 + c]       = ((uint32_t)lo1 << 16) | lo0;
                    *(uint32_t*)&sA1h[(r + 8) * LDA1 + c] = ((uint32_t)h3 << 16) | h2;
                    *(uint32_t*)&sA1l[(r + 8) * LDA1 + c] = ((uint32_t)lo3 << 16) | lo2;
                }
        }

        // ---- GEMM2: Wf = gelu(A1 @ fw2 + fb2); contract with hV ----
        for (int nc2 = 0; nc2 < 3; ++nc2) {
            float acc[2][4][4];
#pragma unroll
            for (int mi = 0; mi < 2; ++mi)
#pragma unroll
                for (int ni = 0; ni < 4; ++ni)
#pragma unroll
                    for (int r = 0; r < 4; ++r) acc[mi][ni][r] = 0.f;

            for (int kc = 0; kc < 3; ++kc) {
                __syncthreads();   // prior W-tile readers done / A1 visible at kc=0
                {
                    // fw2 image: 384 halves/row = 48 uint4 per row; kc*128 halves = kc*16 uint4
                    const uint4* s2h = (const uint4*)g_fw2T_h;
                    const uint4* s2l = (const uint4*)g_fw2T_l;
                    for (int i = tid; i < 2048; i += 256) {
                        int row = i >> 4, c = i & 15;
                        size_t src = (size_t)(nc2 * 128 + row) * 48 + kc * 16 + c;
                        *(uint4*)((char*)sWh + row * (LDW * 2) + c * 16) = s2h[src];
                        *(uint4*)((char*)sWl + row * (LDW * 2) + c * 16) = s2l[src];
                    }
                }
                __syncthreads();
                do_ksteps<LDA1>(sA1h + kc * 128, sA1l + kc * 128, sWh, sWl,
                                m0w, n0w, g, t, acc);
            }

            // epilogue: gelu -> sWf (fp32)
            __syncthreads();   // E-alias region free; all mma reads done
#pragma unroll
            for (int mi = 0; mi < 2; ++mi)
#pragma unroll
                for (int ni = 0; ni < 4; ++ni) {
                    int r  = m0w + mi * 16 + g;
                    int cc = n0w + ni * 8 + t * 2;
                    int c  = nc2 * 128 + cc;
                    float b0 = __ldg(&fb2[c]), b1 = __ldg(&fb2[c + 1]);
                    float2 v01 = make_float2(gelu_f(acc[mi][ni][0] + b0),
                                             gelu_f(acc[mi][ni][1] + b1));
                    float2 v23 = make_float2(gelu_f(acc[mi][ni][2] + b0),
                                             gelu_f(acc[mi][ni][3] + b1));
                    *(float2*)&sWf[r * LDWF + cc]       = v01;
                    *(float2*)&sWf[(r + 8) * LDWF + cc] = v23;
                }
            __syncthreads();

            // x_conv[f] += sum_m Wf[m,f] * hV[b, mt*64+m, f]
            {
                int fl = tid & 127, half = tid >> 7;
                const float* hv = hV + ((size_t)(b * L_) + mt * 64 + half * 32) * F_ + nc2 * 128 + fl;
                float p = 0.f;
#pragma unroll 8
                for (int k = 0; k < 32; ++k)
                    p += hv[(size_t)k * F_] * sWf[(half * 32 + k) * LDWF + fl];
                sPart[half * 128 + fl] = p;
            }
            __syncthreads();
            if (tid < 128) {
                float v = sPart[tid] + sPart[128 + tid];
                if (nc2 == 0)      xacc0 += v;
                else if (nc2 == 1) xacc1 += v;
                else               xacc2 += v;
            }
        }
    }

    // ---- head MLP ----
    __syncthreads();
    if (tid < 128) {
        xcv[tid]       = xacc0;
        xcv[128 + tid] = xacc1;
        xcv[256 + tid] = xacc2;
    }
    __syncthreads();
    if (tid < 128) {
        float s = hb1[tid];
#pragma unroll 4
        for (int i = 0; i < F_; ++i) s += xcv[i] * hw1[i * H_ + tid];
        sH1[tid] = gelu_f(s);
    }
    __syncthreads();
    if (tid < 64) {
        float s = hb2[tid];
#pragma unroll 4
        for (int i = 0; i < H_; ++i) s += sH1[i] * hw2[i * 64 + tid];
        sH2[tid] = gelu_f(s);
    }
    __syncthreads();
    if (tid < 32) {
        float p = sH2[tid] * hw3[tid] + sH2[tid + 32] * hw3[tid + 32];
#pragma unroll
        for (int o = 16; o > 0; o >>= 1) p += __shfl_down_sync(0xffffffffu, p, o);
        if (tid == 0) {
            float pred = p + hb3[0];
            atomicAdd(&g_acc[b], pred * mask[b * L_ + l]);
        }
    }
}

__global__ void finalize_k(const float* __restrict__ mask, float* __restrict__ out) {
    int b = threadIdx.y, lane = threadIdx.x;
    float s = 0.f;
    for (int l = lane; l < L_; l += 32) s += mask[b * L_ + l];
#pragma unroll
    for (int o = 16; o > 0; o >>= 1) s += __shfl_down_sync(0xffffffffu, s, o);
    if (lane == 0) out[b] = g_acc[b] / sqrtf(fmaxf(s, 1.0f));
}

extern "C" void kernel_launch(void* const* d_in, const int* in_sizes, int n_in,
                              void* d_out, int out_size)
{
    const float* hV   = (const float*)d_in[0];
    const float* hE   = (const float*)d_in[1];
    const float* mask = (const float*)d_in[2];
    const float* fw1  = (const float*)d_in[3];
    const float* fb1  = (const float*)d_in[4];
    const float* fw2  = (const float*)d_in[5];
    const float* fb2  = (const float*)d_in[6];
    const float* hw1  = (const float*)d_in[7];
    const float* hb1  = (const float*)d_in[8];
    const float* hw2  = (const float*)d_in[9];
    const float* hb2  = (const float*)d_in[10];
    const float* hw3  = (const float*)d_in[11];
    const float* hb3  = (const float*)d_in[12];
    float* out = (float*)d_out;

    cudaFuncSetAttribute(fused_mma, cudaFuncAttributeMaxDynamicSharedMemorySize, SM_TOTAL);

    prep_weights<<<96, 256>>>(fw1, fw2);
    zero_acc_k<<<1, 32>>>();
    dim3 grid(L_, B_);
    fused_mma<<<grid, 256, SM_TOTAL>>>(hV, hE, mask, fb1, fb2,
                                       hw1, hb1, hw2, hb2, hw3, hb3);
    finalize_k<<<1, dim3(32, B_)>>>(mask, out);
}

// round 5
// speedup vs baseline: 2.8959x; 1.0520x over previous
#include <cuda_runtime.h>
#include <cuda_bf16.h>
#include <math.h>
#include <stdint.h>

#define B_ 4
#define L_ 384
#define H_ 128
#define F_ 384

typedef unsigned short ushort_t;

// ---------------- device scratch: transposed hi/lo bf16 weight images --------
// layout [n][k], k contiguous
__device__ __align__(16) ushort_t g_fw1T_h[F_ * H_];   // 384 x 128
__device__ __align__(16) ushort_t g_fw1T_l[F_ * H_];
__device__ __align__(16) ushort_t g_fw2T_h[F_ * F_];   // 384 x 384
__device__ __align__(16) ushort_t g_fw2T_l[F_ * F_];
__device__ float g_acc[B_];

// ---------------- smem layout (bytes) ----------------------------------------
#define LDE   136   // halves per row (E tiles: 64 x 128)
#define LDW   136   // halves per row (W tiles: 128 x 128)
#define LDA1  392   // halves per row (A1: 64 x 384)
#define LDWF  132   // floats per row (Wf: 64 x 128)

#define SM_E_H   0
#define SM_E_L   17408
#define SM_A1H   34816
#define SM_A1L   84992
#define SM_WH    135168
#define SM_WL    169984
#define SM_XCV   204800
#define SM_PART  206336
#define SM_H1    207360
#define SM_H2    207872
#define SM_TOTAL 208128
// Wf (fp32 64x132 = 33792B) aliases the E region (dead during GEMM2 epilogue).

__device__ __forceinline__ float gelu_f(float x) {
    return 0.5f * x * (1.0f + erff(x * 0.7071067811865475f));
}

__device__ __forceinline__ void split_bf(float x, ushort_t& hi, ushort_t& lo) {
    __nv_bfloat16 h = __float2bfloat16(x);
    __nv_bfloat16 l = __float2bfloat16(x - __bfloat162float(h));
    hi = __bfloat16_as_ushort(h);
    lo = __bfloat16_as_ushort(l);
}

__device__ __forceinline__ uint32_t smem_u32(const void* p) {
    uint32_t a;
    asm("{ .reg .u64 t; cvta.to.shared.u64 t, %1; cvt.u32.u64 %0, t; }" : "=r"(a) : "l"(p));
    return a;
}

#define LDSM4(r, addr) \
    asm volatile("ldmatrix.sync.aligned.m8n8.x4.shared.b16 {%0,%1,%2,%3}, [%4];" \
        : "=r"((r)[0]), "=r"((r)[1]), "=r"((r)[2]), "=r"((r)[3]) : "r"(addr))

#define CP16(dst, src) \
    asm volatile("cp.async.cg.shared.global [%0], [%1], 16;" :: "r"(dst), "l"(src) : "memory")
#define CP_COMMIT() asm volatile("cp.async.commit_group;" ::: "memory")
#define CP_WAIT0()  asm volatile("cp.async.wait_group 0;"  ::: "memory")

__device__ __forceinline__ void mma16816(float d[4], uint32_t a0, uint32_t a1,
                                         uint32_t a2, uint32_t a3,
                                         uint32_t b0, uint32_t b1) {
    asm volatile(
        "mma.sync.aligned.m16n8k16.row.col.f32.bf16.bf16.f32 "
        "{%0,%1,%2,%3}, {%4,%5,%6,%7}, {%8,%9}, {%0,%1,%2,%3};"
        : "+f"(d[0]), "+f"(d[1]), "+f"(d[2]), "+f"(d[3])
        : "r"(a0), "r"(a1), "r"(a2), "r"(a3), "r"(b0), "r"(b1));
}

// 8 k-steps (k=128) of the 3-pass hi/lo MMA over a 32x32 warp tile.
// aH/aL: per-lane ldmatrix base addresses of the A tile (mi=0 group).
// bH/bL: per-lane ldmatrix base addresses of the B tile (ni-pair 0 group).
template <int LDA>
__device__ __forceinline__ void do_ksteps(
    uint32_t aH, uint32_t aL, uint32_t bH, uint32_t bL, float acc[2][4][4])
{
#pragma unroll
    for (int ks = 0; ks < 8; ++ks) {
        uint32_t Ah[2][4], Al[2][4], Bh[2][4], Bl[2][4];
        LDSM4(Ah[0], aH);
        LDSM4(Ah[1], aH + 16 * LDA * 2);
        LDSM4(Al[0], aL);
        LDSM4(Al[1], aL + 16 * LDA * 2);
        LDSM4(Bh[0], bH);
        LDSM4(Bh[1], bH + 16 * LDW * 2);
        LDSM4(Bl[0], bL);
        LDSM4(Bl[1], bL + 16 * LDW * 2);
        aH += 32; aL += 32; bH += 32; bL += 32;
#pragma unroll
        for (int mi = 0; mi < 2; ++mi)
#pragma unroll
            for (int p = 0; p < 2; ++p) {
                // Bh[p] = {b0,b1 of ni=2p ; b0,b1 of ni=2p+1}
                mma16816(acc[mi][2*p], Ah[mi][0], Ah[mi][1], Ah[mi][2], Ah[mi][3],
                         Bh[p][0], Bh[p][1]);
                mma16816(acc[mi][2*p], Ah[mi][0], Ah[mi][1], Ah[mi][2], Ah[mi][3],
                         Bl[p][0], Bl[p][1]);
                mma16816(acc[mi][2*p], Al[mi][0], Al[mi][1], Al[mi][2], Al[mi][3],
                         Bh[p][0], Bh[p][1]);
                mma16816(acc[mi][2*p+1], Ah[mi][0], Ah[mi][1], Ah[mi][2], Ah[mi][3],
                         Bh[p][2], Bh[p][3]);
                mma16816(acc[mi][2*p+1], Ah[mi][0], Ah[mi][1], Ah[mi][2], Ah[mi][3],
                         Bl[p][2], Bl[p][3]);
                mma16816(acc[mi][2*p+1], Al[mi][0], Al[mi][1], Al[mi][2], Al[mi][3],
                         Bh[p][2], Bh[p][3]);
            }
    }
}

// ---------------- weight prep: transpose + hi/lo split ------------------------
__global__ void prep_weights(const float* __restrict__ fw1,
                             const float* __restrict__ fw2) {
    int idx = blockIdx.x * blockDim.x + threadIdx.x;
    int stride = gridDim.x * blockDim.x;
    for (int e = idx; e < F_ * H_; e += stride) {
        int n = e / H_, k = e % H_;
        ushort_t h, l;
        split_bf(fw1[(size_t)k * F_ + n], h, l);
        g_fw1T_h[e] = h; g_fw1T_l[e] = l;
    }
    for (int e = idx; e < F_ * F_; e += stride) {
        int n = e / F_, k = e % F_;
        ushort_t h, l;
        split_bf(fw2[(size_t)k * F_ + n], h, l);
        g_fw2T_h[e] = h; g_fw2T_l[e] = l;
    }
}

__global__ void zero_acc_k() {
    if (threadIdx.x < B_) g_acc[threadIdx.x] = 0.f;
}

__global__ __launch_bounds__(256, 1) void fused_mma(
    const float* __restrict__ hV,  const float* __restrict__ hE,
    const float* __restrict__ mask,
    const float* __restrict__ fb1, const float* __restrict__ fb2,
    const float* __restrict__ hw1, const float* __restrict__ hb1,
    const float* __restrict__ hw2, const float* __restrict__ hb2,
    const float* __restrict__ hw3, const float* __restrict__ hb3)
{
    extern __shared__ char smem[];
    ushort_t* sEh  = (ushort_t*)(smem + SM_E_H);
    ushort_t* sEl  = (ushort_t*)(smem + SM_E_L);
    ushort_t* sA1h = (ushort_t*)(smem + SM_A1H);
    ushort_t* sA1l = (ushort_t*)(smem + SM_A1L);
    float* sWf   = (float*)(smem + SM_E_H);   // alias over E (dead in GEMM2)
    float* xcv   = (float*)(smem + SM_XCV);
    float* sPart = (float*)(smem + SM_PART);
    float* sH1   = (float*)(smem + SM_H1);
    float* sH2   = (float*)(smem + SM_H2);

    const uint32_t sb = smem_u32(smem);

    const int tid  = threadIdx.x;
    const int wid  = tid >> 5;
    const int lane = tid & 31;
    const int g    = lane >> 2;   // groupID
    const int t    = lane & 3;    // thread-in-group
    const int m0w  = (wid >> 2) * 32;
    const int n0w  = (wid & 3) * 32;
    const int l = blockIdx.x, b = blockIdx.y;

    // ldmatrix per-lane addressing
    const int rA = lane & 15;               // A row within 16-row group
    const int kA = (lane >> 4) * 8;         // A k offset (halves)
    const int rB = (lane & 7) + (lane >> 4) * 8;  // B n-row within 16
    const int kB = ((lane >> 3) & 1) * 8;   // B k offset (halves)

    const uint32_t aEh = sb + SM_E_H + ((m0w + rA) * LDE + kA) * 2;
    const uint32_t aEl = sb + SM_E_L + ((m0w + rA) * LDE + kA) * 2;
    const uint32_t aA1h = sb + SM_A1H + ((m0w + rA) * LDA1 + kA) * 2;
    const uint32_t aA1l = sb + SM_A1L + ((m0w + rA) * LDA1 + kA) * 2;
    const uint32_t bWh = sb + SM_WH + ((n0w + rB) * LDW + kB) * 2;
    const uint32_t bWl = sb + SM_WL + ((n0w + rB) * LDW + kB) * 2;

    float xacc0 = 0.f, xacc1 = 0.f, xacc2 = 0.f;
    const float* hE_base = hE + (size_t)(b * L_ + l) * L_ * H_;

    for (int mt = 0; mt < 6; ++mt) {
        // ---- stage E tile [64 x 128] fp32 -> bf16 hi/lo in SMEM ----
        __syncthreads();
        {
            const float* src = hE_base + (size_t)(mt * 64) * H_;
#pragma unroll
            for (int it = 0; it < 8; ++it) {
                int gx = tid + it * 256;          // 0..2047 float4s
                int m = gx >> 5, k4 = (gx & 31) * 4;
                float4 v = *(const float4*)(src + (size_t)m * H_ + k4);
                ushort_t h0, l0, h1, l1, h2, l2, h3, l3;
                split_bf(v.x, h0, l0); split_bf(v.y, h1, l1);
                split_bf(v.z, h2, l2); split_bf(v.w, h3, l3);
                uint32_t ph0 = ((uint32_t)h1 << 16) | h0;
                uint32_t ph1 = ((uint32_t)h3 << 16) | h2;
                uint32_t pl0 = ((uint32_t)l1 << 16) | l0;
                uint32_t pl1 = ((uint32_t)l3 << 16) | l2;
                *(uint2*)&sEh[m * LDE + k4] = make_uint2(ph0, ph1);
                *(uint2*)&sEl[m * LDE + k4] = make_uint2(pl0, pl1);
            }
        }
        __syncthreads();

        // ---- GEMM1: A1 = gelu(E @ fw1 + fb1) -> sA1 hi/lo ----
        for (int nc = 0; nc < 3; ++nc) {
            __syncthreads();   // prior W-tile readers done
            {
                // fw1 image: 128 halves/row = 16 uint4 per row
                const char* s1h = (const char*)g_fw1T_h;
                const char* s1l = (const char*)g_fw1T_l;
#pragma unroll
                for (int it = 0; it < 8; ++it) {
                    int i = tid + it * 256;
                    int row = i >> 4, c = i & 15;
                    uint32_t d = sb + SM_WH + row * (LDW * 2) + c * 16;
                    size_t so = ((size_t)(nc * 128 + row) * 16 + c) * 16;
                    CP16(d, s1h + so);
                    CP16(d + (SM_WL - SM_WH), s1l + so);
                }
            }
            CP_COMMIT(); CP_WAIT0();
            __syncthreads();

            float acc[2][4][4];
#pragma unroll
            for (int mi = 0; mi < 2; ++mi)
#pragma unroll
                for (int ni = 0; ni < 4; ++ni)
#pragma unroll
                    for (int r = 0; r < 4; ++r) acc[mi][ni][r] = 0.f;

            do_ksteps<LDE>(aEh, aEl, bWh, bWl, acc);

            // epilogue: +bias, gelu, split, store
#pragma unroll
            for (int mi = 0; mi < 2; ++mi)
#pragma unroll
                for (int ni = 0; ni < 4; ++ni) {
                    int r = m0w + mi * 16 + g;
                    int c = nc * 128 + n0w + ni * 8 + t * 2;
                    float b0 = __ldg(&fb1[c]), b1 = __ldg(&fb1[c + 1]);
                    float g0 = gelu_f(acc[mi][ni][0] + b0);
                    float g1 = gelu_f(acc[mi][ni][1] + b1);
                    float g2 = gelu_f(acc[mi][ni][2] + b0);
                    float g3 = gelu_f(acc[mi][ni][3] + b1);
                    ushort_t h0, lo0, h1, lo1, h2, lo2, h3, lo3;
                    split_bf(g0, h0, lo0); split_bf(g1, h1, lo1);
                    split_bf(g2, h2, lo2); split_bf(g3, h3, lo3);
                    *(uint32_t*)&sA1h[r * LDA1 + c]       = ((uint32_t)h1 << 16) | h0;
                    *(uint32_t*)&sA1l[r * LDA1 + c]       = ((uint32_t)lo1 << 16) | lo0;
                    *(uint32_t*)&sA1h[(r + 8) * LDA1 + c] = ((uint32_t)h3 << 16) | h2;
                    *(uint32_t*)&sA1l[(r + 8) * LDA1 + c] = ((uint32_t)lo3 << 16) | lo2;
                }
        }

        // ---- GEMM2: Wf = gelu(A1 @ fw2 + fb2); contract with hV ----
        for (int nc2 = 0; nc2 < 3; ++nc2) {
            float acc[2][4][4];
#pragma unroll
            for (int mi = 0; mi < 2; ++mi)
#pragma unroll
                for (int ni = 0; ni < 4; ++ni)
#pragma unroll
                    for (int r = 0; r < 4; ++r) acc[mi][ni][r] = 0.f;

            for (int kc = 0; kc < 3; ++kc) {
                __syncthreads();   // prior W-tile readers done / A1 visible at kc=0
                {
                    // fw2 image: 384 halves/row = 48 uint4/row; kc*128 halves = kc*16 uint4
                    const char* s2h = (const char*)g_fw2T_h;
                    const char* s2l = (const char*)g_fw2T_l;
#pragma unroll
                    for (int it = 0; it < 8; ++it) {
                        int i = tid + it * 256;
                        int row = i >> 4, c = i & 15;
                        uint32_t d = sb + SM_WH + row * (LDW * 2) + c * 16;
                        size_t so = ((size_t)(nc2 * 128 + row) * 48 + kc * 16 + c) * 16;
                        CP16(d, s2h + so);
                        CP16(d + (SM_WL - SM_WH), s2l + so);
                    }
                }
                CP_COMMIT(); CP_WAIT0();
                __syncthreads();
                do_ksteps<LDA1>(aA1h + kc * 256, aA1l + kc * 256, bWh, bWl, acc);
            }

            // epilogue: gelu -> sWf (fp32)
            __syncthreads();   // E-alias region free; all mma reads done
#pragma unroll
            for (int mi = 0; mi < 2; ++mi)
#pragma unroll
                for (int ni = 0; ni < 4; ++ni) {
                    int r  = m0w + mi * 16 + g;
                    int cc = n0w + ni * 8 + t * 2;
                    int c  = nc2 * 128 + cc;
                    float b0 = __ldg(&fb2[c]), b1 = __ldg(&fb2[c + 1]);
                    float2 v01 = make_float2(gelu_f(acc[mi][ni][0] + b0),
                                             gelu_f(acc[mi][ni][1] + b1));
                    float2 v23 = make_float2(gelu_f(acc[mi][ni][2] + b0),
                                             gelu_f(acc[mi][ni][3] + b1));
                    *(float2*)&sWf[r * LDWF + cc]       = v01;
                    *(float2*)&sWf[(r + 8) * LDWF + cc] = v23;
                }
            __syncthreads();

            // x_conv[f] += sum_m Wf[m,f] * hV[b, mt*64+m, f]
            {
                int fl = tid & 127, half = tid >> 7;
                const float* hv = hV + ((size_t)(b * L_) + mt * 64 + half * 32) * F_ + nc2 * 128 + fl;
                float p = 0.f;
#pragma unroll 8
                for (int k = 0; k < 32; ++k)
                    p += hv[(size_t)k * F_] * sWf[(half * 32 + k) * LDWF + fl];
                sPart[half * 128 + fl] = p;
            }
            __syncthreads();
            if (tid < 128) {
                float v = sPart[tid] + sPart[128 + tid];
                if (nc2 == 0)      xacc0 += v;
                else if (nc2 == 1) xacc1 += v;
                else               xacc2 += v;
            }
        }
    }

    // ---- head MLP ----
    __syncthreads();
    if (tid < 128) {
        xcv[tid]       = xacc0;
        xcv[128 + tid] = xacc1;
        xcv[256 + tid] = xacc2;
    }
    __syncthreads();
    if (tid < 128) {
        float s = hb1[tid];
#pragma unroll 4
        for (int i = 0; i < F_; ++i) s += xcv[i] * hw1[i * H_ + tid];
        sH1[tid] = gelu_f(s);
    }
    __syncthreads();
    if (tid < 64) {
        float s = hb2[tid];
#pragma unroll 4
        for (int i = 0; i < H_; ++i) s += sH1[i] * hw2[i * 64 + tid];
        sH2[tid] = gelu_f(s);
    }
    __syncthreads();
    if (tid < 32) {
        float p = sH2[tid] * hw3[tid] + sH2[tid + 32] * hw3[tid + 32];
#pragma unroll
        for (int o = 16; o > 0; o >>= 1) p += __shfl_down_sync(0xffffffffu, p, o);
        if (tid == 0) {
            float pred = p + hb3[0];
            atomicAdd(&g_acc[b], pred * mask[b * L_ + l]);
        }
    }
}

__global__ void finalize_k(const float* __restrict__ mask, float* __restrict__ out) {
    int b = threadIdx.y, lane = threadIdx.x;
    float s = 0.f;
    for (int l = lane; l < L_; l += 32) s += mask[b * L_ + l];
#pragma unroll
    for (int o = 16; o > 0; o >>= 1) s += __shfl_down_sync(0xffffffffu, s, o);
    if (lane == 0) out[b] = g_acc[b] / sqrtf(fmaxf(s, 1.0f));
}

extern "C" void kernel_launch(void* const* d_in, const int* in_sizes, int n_in,
                              void* d_out, int out_size)
{
    const float* hV   = (const float*)d_in[0];
    const float* hE   = (const float*)d_in[1];
    const float* mask = (const float*)d_in[2];
    const float* fw1  = (const float*)d_in[3];
    const float* fb1  = (const float*)d_in[4];
    const float* fw2  = (const float*)d_in[5];
    const float* fb2  = (const float*)d_in[6];
    const float* hw1  = (const float*)d_in[7];
    const float* hb1  = (const float*)d_in[8];
    const float* hw2  = (const float*)d_in[9];
    const float* hb2  = (const float*)d_in[10];
    const float* hw3  = (const float*)d_in[11];
    const float* hb3  = (const float*)d_in[12];
    float* out = (float*)d_out;

    cudaFuncSetAttribute(fused_mma, cudaFuncAttributeMaxDynamicSharedMemorySize, SM_TOTAL);

    prep_weights<<<96, 256>>>(fw1, fw2);
    zero_acc_k<<<1, 32>>>();
    dim3 grid(L_, B_);
    fused_mma<<<grid, 256, SM_TOTAL>>>(hV, hE, mask, fb1, fb2,
                                       hw1, hb1, hw2, hb2, hw3, hb3);
    finalize_k<<<1, dim3(32, B_)>>>(mask, out);
}

// round 6
// speedup vs baseline: 7.0207x; 2.4244x over previous
#include <cuda_runtime.h>
#include <cuda_fp16.h>
#include <math.h>
#include <stdint.h>

#define B_ 4
#define L_ 384
#define H_ 128
#define F_ 384

typedef unsigned short ushort_t;

// ---------------- device scratch: transposed fp16 weight images --------------
// layout [n][k], k contiguous
__device__ __align__(16) ushort_t g_fw1T[F_ * H_];   // 384 x 128
__device__ __align__(16) ushort_t g_fw2T[F_ * F_];   // 384 x 384
__device__ float g_acc[B_];

// ---------------- smem layout (bytes) ----------------------------------------
#define LDE   136   // halves per row (E tile: 64 x 128)
#define LDW   136   // halves per row (W tile: 128 x 128)
#define LDA1  392   // halves per row (A1: 64 x 384)
#define LDWF  132   // floats per row (Wf: 64 x 128)

#define SM_E     0        // 64*136*2  = 17408
#define SM_A1    17408    // 64*392*2  = 50176
#define SM_W     67584    // 128*136*2 = 34816
#define SM_WF    67584    // fp32 64x132 = 33792 (aliases W; W dead at epilogue)
#define SM_XCV   102400   // 384 f
#define SM_PART  103936   // 256 f
#define SM_H1    104960   // 128 f
#define SM_H2    105472   // 64 f
#define SM_TOTAL 105728

__device__ __forceinline__ float gelu_f(float x) {
    return 0.5f * x * (1.0f + erff(x * 0.7071067811865475f));
}

__device__ __forceinline__ uint32_t smem_u32(const void* p) {
    uint32_t a;
    asm("{ .reg .u64 t; cvta.to.shared.u64 t, %1; cvt.u32.u64 %0, t; }" : "=r"(a) : "l"(p));
    return a;
}

#define LDSM4(r, addr) \
    asm volatile("ldmatrix.sync.aligned.m8n8.x4.shared.b16 {%0,%1,%2,%3}, [%4];" \
        : "=r"((r)[0]), "=r"((r)[1]), "=r"((r)[2]), "=r"((r)[3]) : "r"(addr))

#define CP16(dst, src) \
    asm volatile("cp.async.cg.shared.global [%0], [%1], 16;" :: "r"(dst), "l"(src) : "memory")
#define CP_COMMIT() asm volatile("cp.async.commit_group;" ::: "memory")
#define CP_WAIT0()  asm volatile("cp.async.wait_group 0;"  ::: "memory")

__device__ __forceinline__ void mma16816(float d[4], uint32_t a0, uint32_t a1,
                                         uint32_t a2, uint32_t a3,
                                         uint32_t b0, uint32_t b1) {
    asm volatile(
        "mma.sync.aligned.m16n8k16.row.col.f32.f16.f16.f32 "
        "{%0,%1,%2,%3}, {%4,%5,%6,%7}, {%8,%9}, {%0,%1,%2,%3};"
        : "+f"(d[0]), "+f"(d[1]), "+f"(d[2]), "+f"(d[3])
        : "r"(a0), "r"(a1), "r"(a2), "r"(a3), "r"(b0), "r"(b1));
}

__device__ __forceinline__ uint32_t pack_h2(float a, float b) {
    __half2 h = __floats2half2_rn(a, b);
    return *(uint32_t*)&h;
}

// 8 k-steps (k=128) single-pass fp16 MMA over a 32x32 warp tile
template <int LDA>
__device__ __forceinline__ void do_ksteps(uint32_t aA, uint32_t bW, float acc[2][4][4])
{
#pragma unroll
    for (int ks = 0; ks < 8; ++ks) {
        uint32_t A[2][4], Bf[2][4];
        LDSM4(A[0], aA);
        LDSM4(A[1], aA + 16 * LDA * 2);
        LDSM4(Bf[0], bW);
        LDSM4(Bf[1], bW + 16 * LDW * 2);
        aA += 32; bW += 32;
#pragma unroll
        for (int mi = 0; mi < 2; ++mi)
#pragma unroll
            for (int p = 0; p < 2; ++p) {
                mma16816(acc[mi][2*p],   A[mi][0], A[mi][1], A[mi][2], A[mi][3],
                         Bf[p][0], Bf[p][1]);
                mma16816(acc[mi][2*p+1], A[mi][0], A[mi][1], A[mi][2], A[mi][3],
                         Bf[p][2], Bf[p][3]);
            }
    }
}

// ---------------- weight prep: transpose + fp16 convert -----------------------
__global__ void prep_weights(const float* __restrict__ fw1,
                             const float* __restrict__ fw2) {
    int idx = blockIdx.x * blockDim.x + threadIdx.x;
    int stride = gridDim.x * blockDim.x;
    for (int e = idx; e < F_ * H_; e += stride) {
        int n = e / H_, k = e % H_;
        __half h = __float2half_rn(fw1[(size_t)k * F_ + n]);
        g_fw1T[e] = *(ushort_t*)&h;
    }
    for (int e = idx; e < F_ * F_; e += stride) {
        int n = e / F_, k = e % F_;
        __half h = __float2half_rn(fw2[(size_t)k * F_ + n]);
        g_fw2T[e] = *(ushort_t*)&h;
    }
}

__global__ void zero_acc_k() {
    if (threadIdx.x < B_) g_acc[threadIdx.x] = 0.f;
}

__global__ __launch_bounds__(256, 2) void fused_mma(
    const float* __restrict__ hV,  const float* __restrict__ hE,
    const float* __restrict__ mask,
    const float* __restrict__ fb1, const float* __restrict__ fb2,
    const float* __restrict__ hw1, const float* __restrict__ hb1,
    const float* __restrict__ hw2, const float* __restrict__ hb2,
    const float* __restrict__ hw3, const float* __restrict__ hb3)
{
    extern __shared__ char smem[];
    ushort_t* sE  = (ushort_t*)(smem + SM_E);
    ushort_t* sA1 = (ushort_t*)(smem + SM_A1);
    float* sWf   = (float*)(smem + SM_WF);   // alias over W tile
    float* xcv   = (float*)(smem + SM_XCV);
    float* sPart = (float*)(smem + SM_PART);
    float* sH1   = (float*)(smem + SM_H1);
    float* sH2   = (float*)(smem + SM_H2);

    const uint32_t sb = smem_u32(smem);

    const int tid  = threadIdx.x;
    const int wid  = tid >> 5;
    const int lane = tid & 31;
    const int g    = lane >> 2;   // groupID
    const int t    = lane & 3;    // thread-in-group
    const int m0w  = (wid >> 2) * 32;
    const int n0w  = (wid & 3) * 32;
    const int l = blockIdx.x, b = blockIdx.y;

    // ldmatrix per-lane addressing
    const int rA = lane & 15;                      // A row within 16-row group
    const int kA = (lane >> 4) * 8;                // A k offset (halves)
    const int rB = (lane & 7) + (lane >> 4) * 8;   // B n-row within 16
    const int kB = ((lane >> 3) & 1) * 8;          // B k offset (halves)

    const uint32_t aE  = sb + SM_E  + ((m0w + rA) * LDE  + kA) * 2;
    const uint32_t aA1 = sb + SM_A1 + ((m0w + rA) * LDA1 + kA) * 2;
    const uint32_t bW  = sb + SM_W  + ((n0w + rB) * LDW  + kB) * 2;

    float xacc0 = 0.f, xacc1 = 0.f, xacc2 = 0.f;
    const float* hE_base = hE + (size_t)(b * L_ + l) * L_ * H_;

    for (int mt = 0; mt < 6; ++mt) {
        // ---- stage E tile [64 x 128] fp32 -> fp16 in SMEM ----
        __syncthreads();
        {
            const float* src = hE_base + (size_t)(mt * 64) * H_;
#pragma unroll
            for (int it = 0; it < 8; ++it) {
                int gx = tid + it * 256;          // 0..2047 float4s
                int m = gx >> 5, k4 = (gx & 31) * 4;
                float4 v = *(const float4*)(src + (size_t)m * H_ + k4);
                *(uint2*)&sE[m * LDE + k4] =
                    make_uint2(pack_h2(v.x, v.y), pack_h2(v.z, v.w));
            }
        }
        __syncthreads();

        // ---- GEMM1: A1 = gelu(E @ fw1 + fb1) -> sA1 fp16 ----
        for (int nc = 0; nc < 3; ++nc) {
            __syncthreads();   // prior W-tile readers done
            {
                // fw1 image: 128 halves/row = 16 uint4 per row
                const char* s1 = (const char*)g_fw1T;
#pragma unroll
                for (int it = 0; it < 8; ++it) {
                    int i = tid + it * 256;
                    int row = i >> 4, c = i & 15;
                    uint32_t d = sb + SM_W + row * (LDW * 2) + c * 16;
                    CP16(d, s1 + ((size_t)(nc * 128 + row) * 16 + c) * 16);
                }
            }
            CP_COMMIT(); CP_WAIT0();
            __syncthreads();

            float acc[2][4][4];
#pragma unroll
            for (int mi = 0; mi < 2; ++mi)
#pragma unroll
                for (int ni = 0; ni < 4; ++ni)
#pragma unroll
                    for (int r = 0; r < 4; ++r) acc[mi][ni][r] = 0.f;

            do_ksteps<LDE>(aE, bW, acc);

            // epilogue: +bias, gelu, fp16 store
#pragma unroll
            for (int mi = 0; mi < 2; ++mi)
#pragma unroll
                for (int ni = 0; ni < 4; ++ni) {
                    int r = m0w + mi * 16 + g;
                    int c = nc * 128 + n0w + ni * 8 + t * 2;
                    float b0 = __ldg(&fb1[c]), b1 = __ldg(&fb1[c + 1]);
                    float g0 = gelu_f(acc[mi][ni][0] + b0);
                    float g1 = gelu_f(acc[mi][ni][1] + b1);
                    float g2 = gelu_f(acc[mi][ni][2] + b0);
                    float g3 = gelu_f(acc[mi][ni][3] + b1);
                    *(uint32_t*)&sA1[r * LDA1 + c]       = pack_h2(g0, g1);
                    *(uint32_t*)&sA1[(r + 8) * LDA1 + c] = pack_h2(g2, g3);
                }
        }

        // ---- GEMM2: Wf = gelu(A1 @ fw2 + fb2); contract with hV ----
        for (int nc2 = 0; nc2 < 3; ++nc2) {
            float acc[2][4][4];
#pragma unroll
            for (int mi = 0; mi < 2; ++mi)
#pragma unroll
                for (int ni = 0; ni < 4; ++ni)
#pragma unroll
                    for (int r = 0; r < 4; ++r) acc[mi][ni][r] = 0.f;

            for (int kc = 0; kc < 3; ++kc) {
                __syncthreads();   // prior W-tile/Wf readers done; A1 visible at kc=0
                {
                    // fw2 image: 384 halves/row = 48 uint4/row
                    const char* s2 = (const char*)g_fw2T;
#pragma unroll
                    for (int it = 0; it < 8; ++it) {
                        int i = tid + it * 256;
                        int row = i >> 4, c = i & 15;
                        uint32_t d = sb + SM_W + row * (LDW * 2) + c * 16;
                        CP16(d, s2 + ((size_t)(nc2 * 128 + row) * 48 + kc * 16 + c) * 16);
                    }
                }
                CP_COMMIT(); CP_WAIT0();
                __syncthreads();
                do_ksteps<LDA1>(aA1 + kc * 256, bW, acc);
            }

            // epilogue: gelu -> sWf (fp32, aliases W tile which is now dead)
            __syncthreads();
#pragma unroll
            for (int mi = 0; mi < 2; ++mi)
#pragma unroll
                for (int ni = 0; ni < 4; ++ni) {
                    int r  = m0w + mi * 16 + g;
                    int cc = n0w + ni * 8 + t * 2;
                    int c  = nc2 * 128 + cc;
                    float b0 = __ldg(&fb2[c]), b1 = __ldg(&fb2[c + 1]);
                    float2 v01 = make_float2(gelu_f(acc[mi][ni][0] + b0),
                                             gelu_f(acc[mi][ni][1] + b1));
                    float2 v23 = make_float2(gelu_f(acc[mi][ni][2] + b0),
                                             gelu_f(acc[mi][ni][3] + b1));
                    *(float2*)&sWf[r * LDWF + cc]       = v01;
                    *(float2*)&sWf[(r + 8) * LDWF + cc] = v23;
                }
            __syncthreads();

            // x_conv[f] += sum_m Wf[m,f] * hV[b, mt*64+m, f]
            {
                int fl = tid & 127, half = tid >> 7;
                const float* hv = hV + ((size_t)(b * L_) + mt * 64 + half * 32) * F_ + nc2 * 128 + fl;
                float p = 0.f;
#pragma unroll 8
                for (int k = 0; k < 32; ++k)
                    p += hv[(size_t)k * F_] * sWf[(half * 32 + k) * LDWF + fl];
                sPart[half * 128 + fl] = p;
            }
            __syncthreads();
            if (tid < 128) {
                float v = sPart[tid] + sPart[128 + tid];
                if (nc2 == 0)      xacc0 += v;
                else if (nc2 == 1) xacc1 += v;
                else               xacc2 += v;
            }
        }
    }

    // ---- head MLP ----
    __syncthreads();
    if (tid < 128) {
        xcv[tid]       = xacc0;
        xcv[128 + tid] = xacc1;
        xcv[256 + tid] = xacc2;
    }
    __syncthreads();
    if (tid < 128) {
        float s = hb1[tid];
#pragma unroll 4
        for (int i = 0; i < F_; ++i) s += xcv[i] * hw1[i * H_ + tid];
        sH1[tid] = gelu_f(s);
    }
    __syncthreads();
    if (tid < 64) {
        float s = hb2[tid];
#pragma unroll 4
        for (int i = 0; i < H_; ++i) s += sH1[i] * hw2[i * 64 + tid];
        sH2[tid] = gelu_f(s);
    }
    __syncthreads();
    if (tid < 32) {
        float p = sH2[tid] * hw3[tid] + sH2[tid + 32] * hw3[tid + 32];
#pragma unroll
        for (int o = 16; o > 0; o >>= 1) p += __shfl_down_sync(0xffffffffu, p, o);
        if (tid == 0) {
            float pred = p + hb3[0];
            atomicAdd(&g_acc[b], pred * mask[b * L_ + l]);
        }
    }
}

__global__ void finalize_k(const float* __restrict__ mask, float* __restrict__ out) {
    int b = threadIdx.y, lane = threadIdx.x;
    float s = 0.f;
    for (int l = lane; l < L_; l += 32) s += mask[b * L_ + l];
#pragma unroll
    for (int o = 16; o > 0; o >>= 1) s += __shfl_down_sync(0xffffffffu, s, o);
    if (lane == 0) out[b] = g_acc[b] / sqrtf(fmaxf(s, 1.0f));
}

extern "C" void kernel_launch(void* const* d_in, const int* in_sizes, int n_in,
                              void* d_out, int out_size)
{
    const float* hV   = (const float*)d_in[0];
    const float* hE   = (const float*)d_in[1];
    const float* mask = (const float*)d_in[2];
    const float* fw1  = (const float*)d_in[3];
    const float* fb1  = (const float*)d_in[4];
    const float* fw2  = (const float*)d_in[5];
    const float* fb2  = (const float*)d_in[6];
    const float* hw1  = (const float*)d_in[7];
    const float* hb1  = (const float*)d_in[8];
    const float* hw2  = (const float*)d_in[9];
    const float* hb2  = (const float*)d_in[10];
    const float* hw3  = (const float*)d_in[11];
    const float* hb3  = (const float*)d_in[12];
    float* out = (float*)d_out;

    cudaFuncSetAttribute(fused_mma, cudaFuncAttributeMaxDynamicSharedMemorySize, SM_TOTAL);

    prep_weights<<<96, 256>>>(fw1, fw2);
    zero_acc_k<<<1, 32>>>();
    dim3 grid(L_, B_);
    fused_mma<<<grid, 256, SM_TOTAL>>>(hV, hE, mask, fb1, fb2,
                                       hw1, hb1, hw2, hb2, hw3, hb3);
    finalize_k<<<1, dim3(32, B_)>>>(mask, out);
}